// round 1
// baseline (speedup 1.0000x reference)
#include <cuda_runtime.h>

#define NCAM 6
#define CCH  128
#define H0   32
#define W0   88
#define H1   16
#define W1   44
#define QDIM 16384
#define PPTS 4
#define EPSF 1e-5f

// Transposed feature scratch: [N, H, W, C] so channel gathers are contiguous.
__device__ float g_f0t[NCAM * H0 * W0 * CCH];   // ~8.65 MB
__device__ float g_f1t[NCAM * H1 * W1 * CCH];   // ~2.16 MB

// -------------------------------------------------------------------------
// Pre-pass: [N,C,H,W] -> [N,H,W,C]. Output-linear indexing => coalesced
// writes; strided reads are absorbed by L2 (whole input ~10.8 MB).
// -------------------------------------------------------------------------
__global__ void transpose_feats_kernel(const float* __restrict__ f0,
                                       const float* __restrict__ f1) {
    const int total0 = NCAM * H0 * W0 * CCH;
    const int total1 = NCAM * H1 * W1 * CCH;
    for (int idx = blockIdx.x * blockDim.x + threadIdx.x;
         idx < total0 + total1;
         idx += gridDim.x * blockDim.x) {
        if (idx < total0) {
            int c = idx & (CCH - 1);
            int rest = idx >> 7;            // / CCH
            int w = rest % W0; rest /= W0;
            int h = rest % H0;
            int n = rest / H0;
            g_f0t[idx] = f0[((n * CCH + c) * H0 + h) * W0 + w];
        } else {
            int j = idx - total0;
            int c = j & (CCH - 1);
            int rest = j >> 7;
            int w = rest % W1; rest /= W1;
            int h = rest % H1;
            int n = rest / H1;
            g_f1t[j] = f1[((n * CCH + c) * H1 + h) * W1 + w];
        }
    }
}

__device__ __forceinline__ void f4axpy(float4& acc, float wgt, const float4 v) {
    acc.x = fmaf(wgt, v.x, acc.x);
    acc.y = fmaf(wgt, v.y, acc.y);
    acc.z = fmaf(wgt, v.z, acc.z);
    acc.w = fmaf(wgt, v.w, acc.w);
}

// Bilinear sample (zero padding, align_corners=False) of 4 channels (cb..cb+3)
// from transposed layout [H,W,C]. u,v in (0,1).
__device__ __forceinline__ void bilin4(const float* __restrict__ base,
                                       int Wl, int Hl,
                                       float u, float v, int cb,
                                       float4& acc) {
    float px = u * (float)Wl - 0.5f;
    float py = v * (float)Hl - 0.5f;
    float x0f = floorf(px);
    float y0f = floorf(py);
    int x0 = (int)x0f, y0 = (int)y0f;
    int x1 = x0 + 1,   y1 = y0 + 1;
    float wx1 = px - x0f, wx0 = 1.0f - wx1;
    float wy1 = py - y0f, wy0 = 1.0f - wy1;

    // u in (0,1) => x0 in [-1, Wl-1], x1 in [0, Wl]; same for y.
    bool vx0 = (x0 >= 0);
    bool vx1 = (x1 <= Wl - 1);
    bool vy0 = (y0 >= 0);
    bool vy1 = (y1 <= Hl - 1);

    if (vy0) {
        const float* row = base + (y0 * Wl) * CCH;
        if (vx0) f4axpy(acc, wx0 * wy0, *(const float4*)(row + x0 * CCH + cb));
        if (vx1) f4axpy(acc, wx1 * wy0, *(const float4*)(row + x1 * CCH + cb));
    }
    if (vy1) {
        const float* row = base + (y1 * Wl) * CCH;
        if (vx0) f4axpy(acc, wx0 * wy1, *(const float4*)(row + x0 * CCH + cb));
        if (vx1) f4axpy(acc, wx1 * wy1, *(const float4*)(row + x1 * CCH + cb));
    }
}

// -------------------------------------------------------------------------
// Main: 1 warp per (q,p) task. Lane l owns channels [4l, 4l+4).
// Output layout [B=1, Q, P, C] => task = q*P + p, contiguous C.
// -------------------------------------------------------------------------
__global__ void __launch_bounds__(256)
bev_sample_kernel(const float* __restrict__ refpts,
                  const float* __restrict__ lidar2img,
                  float* __restrict__ out) {
    __shared__ float sM[NCAM * 16];
    if (threadIdx.x < NCAM * 16) sM[threadIdx.x] = lidar2img[threadIdx.x];
    __syncthreads();

    int warp = blockIdx.x * (blockDim.x >> 5) + (threadIdx.x >> 5);
    int lane = threadIdx.x & 31;
    if (warp >= QDIM * PPTS) return;

    int task = warp;
    int q = task >> 2;          // / PPTS
    int p = task & 3;
    int hb = q >> 7;            // / 128
    int wb = q & 127;

    // reference_points layout [B=1, P, Hb, Wb, 3]
    const float* rp = refpts + ((size_t)((p * 128 + hb) * 128 + wb)) * 3;
    float X = __ldg(rp + 0) * 102.4f - 51.2f;
    float Y = __ldg(rp + 1) * 102.4f - 51.2f;
    float Z = __ldg(rp + 2) * 8.0f  - 5.0f;

    int cb = lane * 4;
    float4 acc = make_float4(0.f, 0.f, 0.f, 0.f);
    int cnt = 0;

#pragma unroll
    for (int n = 0; n < NCAM; n++) {
        const float* M = sM + n * 16;
        float cz = M[8] * X + M[9] * Y + M[10] * Z + M[11];
        if (cz > EPSF) {
            float cx = M[0] * X + M[1] * Y + M[2] * Z + M[3];
            float cy = M[4] * X + M[5] * Y + M[6] * Z + M[7];
            float u = cx / (cz * 704.0f);   // IMG_W
            float v = cy / (cz * 256.0f);   // IMG_H
            if (u > 0.0f && u < 1.0f && v > 0.0f && v < 1.0f) {
                cnt++;
                bilin4(g_f0t + (size_t)n * H0 * W0 * CCH, W0, H0, u, v, cb, acc);
                bilin4(g_f1t + (size_t)n * H1 * W1 * CCH, W1, H1, u, v, cb, acc);
            }
        }
    }

    // sampled = (lvl0 + lvl1)/2 ; out = sum_valid(sampled) / max(cnt,1)
    float den = (float)(cnt > 0 ? cnt : 1);
    float scale = 1.0f / (2.0f * den);
    float4 o;
    o.x = acc.x * scale;
    o.y = acc.y * scale;
    o.z = acc.z * scale;
    o.w = acc.w * scale;
    *(float4*)(out + (size_t)task * CCH + cb) = o;
}

extern "C" void kernel_launch(void* const* d_in, const int* in_sizes, int n_in,
                              void* d_out, int out_size) {
    const float* refpts    = (const float*)d_in[0];   // [1,4,128,128,3]
    const float* feats0    = (const float*)d_in[1];   // [1,6,128,32,88]
    const float* feats1    = (const float*)d_in[2];   // [1,6,128,16,44]
    const float* lidar2img = (const float*)d_in[3];   // [1,6,4,4]
    float* out = (float*)d_out;                       // [1,16384,4,128]

    // Pre-pass transpose (both levels in one grid-stride kernel).
    transpose_feats_kernel<<<4096, 256>>>(feats0, feats1);

    // 65536 tasks, 8 warps/block -> 8192 blocks.
    bev_sample_kernel<<<(QDIM * PPTS) / 8, 256>>>(refpts, lidar2img, out);
}

// round 2
// speedup vs baseline: 1.5573x; 1.5573x over previous
#include <cuda_runtime.h>

#define NCAM 6
#define CCH  128
#define H0   32
#define W0   88
#define H1   16
#define W1   44
#define HW0  (H0*W0)      // 2816
#define HW1  (H1*W1)      // 704
#define QDIM 16384
#define PPTS 4
#define EPSF 1e-5f
#define FULLMASK 0xffffffffu

// Transposed feature scratch: [N, H, W, C] so channel gathers are contiguous.
__device__ float g_f0t[NCAM * HW0 * CCH];   // ~8.65 MB
__device__ float g_f1t[NCAM * HW1 * CCH];   // ~2.16 MB

// -------------------------------------------------------------------------
// SMEM-tiled transpose: per camera n, transpose [C=128, HW] -> [HW, C].
// 32x32 tiles, coalesced on both sides.
// Level0: 6 cams * 4 c-tiles * 88 hw-tiles = 2112 blocks
// Level1: 6 cams * 4 c-tiles * 22 hw-tiles =  528 blocks
// -------------------------------------------------------------------------
#define NBLK0 (NCAM * 4 * (HW0/32))   // 2112
#define NBLK1 (NCAM * 4 * (HW1/32))   // 528

__global__ void __launch_bounds__(256)
transpose_feats_kernel(const float* __restrict__ f0,
                       const float* __restrict__ f1) {
    __shared__ float tile[32][33];
    int tx = threadIdx.x & 31;
    int ty = threadIdx.x >> 5;            // 0..7

    int b = blockIdx.x;
    const float* __restrict__ src;
    float* __restrict__ dst;
    int n, ct, hwt, HW;
    if (b < NBLK0) {
        n = b / (4 * (HW0/32));
        int r = b % (4 * (HW0/32));
        ct = r & 3;
        hwt = r >> 2;
        src = f0; dst = g_f0t; HW = HW0;
    } else {
        b -= NBLK0;
        n = b / (4 * (HW1/32));
        int r = b % (4 * (HW1/32));
        ct = r & 3;
        hwt = r >> 2;
        src = f1; dst = g_f1t; HW = HW1;
    }

    // Read: row = channel, col = hw (coalesced in hw)
    const float* sp = src + (size_t)n * CCH * HW + (ct*32) * HW + hwt*32;
#pragma unroll
    for (int i = 0; i < 4; i++) {
        int c = ty + i*8;
        tile[c][tx] = sp[c * HW + tx];
    }
    __syncthreads();

    // Write: row = hw, col = channel (coalesced in channel)
    float* dp = dst + (size_t)n * HW * CCH + (hwt*32) * CCH + ct*32;
#pragma unroll
    for (int i = 0; i < 4; i++) {
        int hw = ty + i*8;
        dp[hw * CCH + tx] = tile[tx][hw];
    }
}

// -------------------------------------------------------------------------
// Main sampling kernel.
// -------------------------------------------------------------------------
struct LP {
    int   o00, o01, o10, o11;   // corner offsets in floats (include cam base)
    float w00, w01, w10, w11;   // bilinear weights (zeroed at borders)
};

__device__ __forceinline__ LP mkparams(float u, float v, int cam, int Wl, int Hl) {
    LP p;
    float px = u * (float)Wl - 0.5f;
    float py = v * (float)Hl - 0.5f;
    float x0f = floorf(px);
    float y0f = floorf(py);
    float wx1 = px - x0f, wx0 = 1.0f - wx1;
    float wy1 = py - y0f, wy0 = 1.0f - wy1;
    int x0 = (int)x0f, y0 = (int)y0f;
    int x1 = x0 + 1,   y1 = y0 + 1;
    // u,v in (0,1) => only -1 underflow / W overflow possible
    if (x0 < 0)      { wx0 = 0.0f; x0 = 0; }
    if (x1 > Wl - 1) { wx1 = 0.0f; x1 = Wl - 1; }
    if (y0 < 0)      { wy0 = 0.0f; y0 = 0; }
    if (y1 > Hl - 1) { wy1 = 0.0f; y1 = Hl - 1; }
    int base = cam * Hl * Wl;
    int r0 = (base + y0 * Wl) * CCH;
    int r1 = (base + y1 * Wl) * CCH;
    int c0 = x0 * CCH;
    int c1 = x1 * CCH;
    p.o00 = r0 + c0; p.o01 = r0 + c1;
    p.o10 = r1 + c0; p.o11 = r1 + c1;
    p.w00 = wx0 * wy0; p.w01 = wx1 * wy0;
    p.w10 = wx0 * wy1; p.w11 = wx1 * wy1;
    return p;
}

// Packed f32x2 weighted accumulate of 4 contiguous floats.
__device__ __forceinline__ void gacc(const float* __restrict__ ptr, float w,
                                     unsigned long long& aA, unsigned long long& aB) {
    ulonglong2 v = *reinterpret_cast<const ulonglong2*>(ptr);
    unsigned long long wp;
    asm("mov.b64 %0, {%1, %1};" : "=l"(wp) : "f"(w));
    asm("fma.rn.f32x2 %0, %1, %2, %0;" : "+l"(aA) : "l"(v.x), "l"(wp));
    asm("fma.rn.f32x2 %0, %1, %2, %0;" : "+l"(aB) : "l"(v.y), "l"(wp));
}

__device__ __forceinline__ void gather_lv(const LP& p, int src,
                                          const float* __restrict__ base, int cb,
                                          unsigned long long& aA, unsigned long long& aB) {
    int a00 = __shfl_sync(FULLMASK, p.o00, src);
    int a01 = __shfl_sync(FULLMASK, p.o01, src);
    int a10 = __shfl_sync(FULLMASK, p.o10, src);
    int a11 = __shfl_sync(FULLMASK, p.o11, src);
    float s00 = __shfl_sync(FULLMASK, p.w00, src);
    float s01 = __shfl_sync(FULLMASK, p.w01, src);
    float s10 = __shfl_sync(FULLMASK, p.w10, src);
    float s11 = __shfl_sync(FULLMASK, p.w11, src);
    gacc(base + a00 + cb, s00, aA, aB);
    gacc(base + a01 + cb, s01, aA, aB);
    gacc(base + a10 + cb, s10, aA, aB);
    gacc(base + a11 + cb, s11, aA, aB);
}

__global__ void __launch_bounds__(256)
bev_sample_kernel(const float* __restrict__ refpts,
                  const float* __restrict__ lidar2img,
                  float* __restrict__ out) {
    __shared__ float sM[NCAM * 16];
    if (threadIdx.x < NCAM * 16) sM[threadIdx.x] = lidar2img[threadIdx.x];
    __syncthreads();

    int warp = blockIdx.x * (blockDim.x >> 5) + (threadIdx.x >> 5);
    int lane = threadIdx.x & 31;
    int task = warp;

    int q = task >> 2;
    int p = task & 3;
    int hb = q >> 7;
    int wb = q & 127;

    // reference_points layout [B=1, P, Hb, Wb, 3] — uniform per warp
    const float* rp = refpts + ((size_t)((p * 128 + hb) * 128 + wb)) * 3;
    float X = __ldg(rp + 0) * 102.4f - 51.2f;
    float Y = __ldg(rp + 1) * 102.4f - 51.2f;
    float Z = __ldg(rp + 2) * 8.0f  - 5.0f;

    // Lanes 0..5 each compute one camera's projection + bilinear params
    bool valid = false;
    LP p0, p1;
    if (lane < NCAM) {
        const float* M = sM + lane * 16;
        float cz = fmaf(M[8], X, fmaf(M[9], Y, fmaf(M[10], Z, M[11])));
        if (cz > EPSF) {
            float cx = fmaf(M[0], X, fmaf(M[1], Y, fmaf(M[2], Z, M[3])));
            float cy = fmaf(M[4], X, fmaf(M[5], Y, fmaf(M[6], Z, M[7])));
            float invz = __fdividef(1.0f, cz);
            float u = cx * invz * (1.0f / 704.0f);
            float v = cy * invz * (1.0f / 256.0f);
            if (u > 0.0f && u < 1.0f && v > 0.0f && v < 1.0f) {
                valid = true;
                p0 = mkparams(u, v, lane, W0, H0);
                p1 = mkparams(u, v, lane, W1, H1);
            }
        }
    }

    unsigned vm = __ballot_sync(FULLMASK, valid);
    int cnt = __popc(vm);

    int cb = lane * 4;
    unsigned long long aA = 0ull, aB = 0ull;   // packed fp32x2 accumulators

    while (vm) {
        int src = __ffs(vm) - 1;
        vm &= vm - 1;
        gather_lv(p0, src, g_f0t, cb, aA, aB);
        gather_lv(p1, src, g_f1t, cb, aA, aB);
    }

    // sampled = (lvl0+lvl1)/2; out = sum / max(cnt,1)
    float scale = 0.5f / fmaxf((float)cnt, 1.0f);
    float ax, ay, az, aw;
    asm("mov.b64 {%0, %1}, %2;" : "=f"(ax), "=f"(ay) : "l"(aA));
    asm("mov.b64 {%0, %1}, %2;" : "=f"(az), "=f"(aw) : "l"(aB));
    float4 o;
    o.x = ax * scale; o.y = ay * scale;
    o.z = az * scale; o.w = aw * scale;
    *reinterpret_cast<float4*>(out + (size_t)task * CCH + cb) = o;
}

extern "C" void kernel_launch(void* const* d_in, const int* in_sizes, int n_in,
                              void* d_out, int out_size) {
    const float* refpts    = (const float*)d_in[0];   // [1,4,128,128,3]
    const float* feats0    = (const float*)d_in[1];   // [1,6,128,32,88]
    const float* feats1    = (const float*)d_in[2];   // [1,6,128,16,44]
    const float* lidar2img = (const float*)d_in[3];   // [1,6,4,4]
    float* out = (float*)d_out;                       // [1,16384,4,128]

    transpose_feats_kernel<<<NBLK0 + NBLK1, 256>>>(feats0, feats1);
    bev_sample_kernel<<<(QDIM * PPTS) / 8, 256>>>(refpts, lidar2img, out);
}